// round 7
// baseline (speedup 1.0000x reference)
#include <cuda_runtime.h>
#include <cuda_bf16.h>
#include <cstdint>

#define MDIM  128
#define FEAT  8256          // MDIM*(MDIM+1)/2
#define HID   1651
#define NP    1664          // HID padded to 26*64
#define KP    8320          // FEAT padded to 65*128
#define BATCH 4096
#define KST   65            // KP / 128

#define SX        16.0f     // x quant scale
#define SW        1048576.0f// w1 quant scale (2^20)
#define INV_S     (1.0f/(16.0f*1048576.0f))

#define A_BYTES     16384   // 128 rows x 128B
#define B_BYTES     8192    // 64 rows x 128B
#define STAGE_BYTES (A_BYTES + B_BYTES)   // 24 KB
#define NSTAGE      3
#define SMEM_TOTAL  (NSTAGE * STAGE_BYTES)   // 72 KB

#define MT 32               // M tiles (4096/128)
#define NT 26               // N tiles (1664/64)
#define NTILES (MT*NT)      // 832
#define GRID   444          // 148 SMs * 3 CTAs

// ---------------- device scratch ----------------
__device__ int8_t g_x8 [(size_t)BATCH * KP];   // 34.1 MB
__device__ int8_t g_w18[(size_t)NP    * KP];   // 13.8 MB
__device__ float g_b1[NP];
__device__ float g_w2[NP];
__device__ float g_logits[BATCH];

// ---------------- helpers ----------------
__device__ __forceinline__ uint32_t smem_u32(const void* p) {
    uint32_t a;
    asm("{ .reg .u64 t; cvta.to.shared.u64 t, %1; cvt.u32.u64 %0, t; }" : "=r"(a) : "l"(p));
    return a;
}
#define SWZ128(off) ((off) ^ (((off) >> 3) & 0x70))

__device__ __forceinline__ void ldsm_x4(uint32_t& r0, uint32_t& r1, uint32_t& r2, uint32_t& r3,
                                        uint32_t addr) {
    asm volatile("ldmatrix.sync.aligned.m8n8.x4.shared.b16 {%0,%1,%2,%3}, [%4];"
                 : "=r"(r0), "=r"(r1), "=r"(r2), "=r"(r3) : "r"(addr));
}
__device__ __forceinline__ void mma_s8(int* c, const uint32_t* a, const uint32_t* b) {
    asm volatile(
        "mma.sync.aligned.m16n8k32.row.col.s32.s8.s8.s32 "
        "{%0,%1,%2,%3}, {%4,%5,%6,%7}, {%8,%9}, {%0,%1,%2,%3};"
        : "+r"(c[0]), "+r"(c[1]), "+r"(c[2]), "+r"(c[3])
        : "r"(a[0]), "r"(a[1]), "r"(a[2]), "r"(a[3]), "r"(b[0]), "r"(b[1]));
}
__device__ __forceinline__ uint8_t q8(float v, float s) {
    int t = __float2int_rn(v * s);
    t = max(-127, min(127, t));
    return (uint8_t)(int8_t)t;
}

// ---------------- prep kernels ----------------
__global__ void prep_small(const float* __restrict__ b1, const float* __restrict__ w2) {
    int i = blockIdx.x * blockDim.x + threadIdx.x;
    if (i < NP) {
        g_b1[i] = (i < HID) ? b1[i] : 0.0f;
        g_w2[i] = (i < HID) ? w2[i] : 0.0f;
    }
    if (i < BATCH) g_logits[i] = 0.0f;
}

// W1 fp32 -> int8 (scaled by 2^20)
__global__ void prep_w18(const float* __restrict__ W1) {
    int n  = blockIdx.y;
    int k4 = blockIdx.x * blockDim.x + threadIdx.x;
    if (k4 >= KP / 4) return;
    uint32_t out = 0;
    if (n < HID) {
        int k = k4 * 4;
        if (k + 3 < FEAT) {
            float4 v = *(const float4*)&W1[(size_t)n * FEAT + k];
            out  = (uint32_t)q8(v.x, SW);
            out |= (uint32_t)q8(v.y, SW) << 8;
            out |= (uint32_t)q8(v.z, SW) << 16;
            out |= (uint32_t)q8(v.w, SW) << 24;
        } else {
#pragma unroll
            for (int j = 0; j < 4; j++) {
                float v = (k + j < FEAT) ? W1[(size_t)n * FEAT + k + j] : 0.0f;
                out |= (uint32_t)q8(v, SW) << (8 * j);
            }
        }
    }
    ((uint32_t*)g_w18)[(size_t)n * (KP / 4) + k4] = out;
}

// triu extraction + int8 quant (scale 16)
__global__ __launch_bounds__(256) void triu8(const float* __restrict__ sim) {
    int b   = blockIdx.x;
    int tid = threadIdx.x;
    const float* base = sim + (size_t)b * MDIM * MDIM;
    int8_t* out = g_x8 + (size_t)b * KP;
#pragma unroll
    for (int it = 0; it < 16; ++it) {
        int idx = tid + it * 256;       // 0..4095: (row, group-of-4)
        int i = idx >> 5;
        int g = idx & 31;
        int j0 = g * 4;
        if (j0 + 3 >= i) {
            float4 v = *(const float4*)&base[i * MDIM + j0];
            int rowoff = i * MDIM - (i * (i - 1)) / 2 - i;   // out index = rowoff + j
            float vv[4] = {v.x, v.y, v.z, v.w};
#pragma unroll
            for (int l = 0; l < 4; l++) {
                int j = j0 + l;
                if (j >= i) out[rowoff + j] = (int8_t)q8(vv[l], SX);
            }
        }
    }
    if (tid < KP - FEAT) out[FEAT + tid] = 0;
}

// ---------------- int8 GEMM: persistent, CTA 128x64, 4 warps (32x64), 3 CTA/SM ----------------
__global__ __launch_bounds__(128, 3) void gemm_i8() {
    extern __shared__ __align__(1024) uint8_t smem[];
    const uint32_t sbase = smem_u32(smem);
    const int tid = threadIdx.x;
    const int wid = tid >> 5;
    const int lid = tid & 31;

    // ---- hoisted ldmatrix addressing (swizzle decomposed: row-invariant XOR mask) ----
    // A: warp wid covers rows [wid*32, wid*32+32); +2048*mi (16 rows, keeps row&7)
    const int aRow0 = wid * 32 + ((lid >> 3) & 1) * 8 + (lid & 7);
    const int aCol  = (lid >> 4) * 16;
    const uint32_t aXor = (uint32_t)((aRow0 & 7) << 4);
    // B: 64 shared rows; +2048*p
    const int bRow0 = (lid >> 4) * 8 + (lid & 7);
    const int bCol  = ((lid >> 3) & 1) * 16;
    const uint32_t bXor = (uint32_t)((bRow0 & 7) << 4);

    uint32_t aOff[4], bOff[4];
#pragma unroll
    for (int ks = 0; ks < 4; ks++) {
        aOff[ks] = (uint32_t)(aRow0 * 128) + (((uint32_t)(aCol + ks * 32)) ^ aXor);
        bOff[ks] = A_BYTES + (uint32_t)(bRow0 * 128) + (((uint32_t)(bCol + ks * 32)) ^ bXor);
    }

    for (int t = blockIdx.x; t < NTILES; t += GRID) {
        const int m0 = (t / NT) * 128;
        const int n0 = (t % NT) * 64;

        int acc[2][8][4];
#pragma unroll
        for (int mi = 0; mi < 2; mi++)
#pragma unroll
            for (int ni = 0; ni < 8; ni++)
#pragma unroll
                for (int c = 0; c < 4; c++) acc[mi][ni][c] = 0;

        auto load_stage = [&](int buf, int kByte) {
            uint32_t st = sbase + buf * STAGE_BYTES;
            // A: 1024 chunks (128 rows x 8), B: 512 chunks (64 x 8); 12/thread
#pragma unroll
            for (int it = 0; it < 12; ++it) {
                int idx = tid + it * 128;           // 0..1535
                bool isB = idx >= 1024;
                int rel  = isB ? (idx - 1024) : idx;
                int r    = rel >> 3;
                int c    = rel & 7;
                const int8_t* src = isB
                    ? &g_w18[(size_t)(n0 + r) * KP + kByte + c * 16]
                    : &g_x8 [(size_t)(m0 + r) * KP + kByte + c * 16];
                uint32_t dst = st + (isB ? A_BYTES : 0) + SWZ128((uint32_t)(r * 128 + c * 16));
                asm volatile("cp.async.cg.shared.global [%0], [%1], 16;"
                             :: "r"(dst), "l"(src) : "memory");
            }
            asm volatile("cp.async.commit_group;" ::: "memory");
        };

        load_stage(0, 0);
        load_stage(1, 128);

        for (int s = 0; s < KST; ++s) {
            asm volatile("cp.async.wait_group 1;" ::: "memory");
            __syncthreads();

            if (s + 2 < KST) load_stage((s + 2) % NSTAGE, (s + 2) * 128);
            else             asm volatile("cp.async.commit_group;" ::: "memory");

            const uint32_t stg = sbase + (s % NSTAGE) * STAGE_BYTES;

#pragma unroll
            for (int ks = 0; ks < 4; ++ks) {
                uint32_t b[8][2];
#pragma unroll
                for (int p = 0; p < 4; p++) {
                    uint32_t r0, r1, r2, r3;
                    ldsm_x4(r0, r1, r2, r3, stg + bOff[ks] + p * 2048);
                    b[2 * p][0] = r0; b[2 * p][1] = r1;
                    b[2 * p + 1][0] = r2; b[2 * p + 1][1] = r3;
                }
                uint32_t a[2][4];
                ldsm_x4(a[0][0], a[0][1], a[0][2], a[0][3], stg + aOff[ks]);
                ldsm_x4(a[1][0], a[1][1], a[1][2], a[1][3], stg + aOff[ks] + 2048);
#pragma unroll
                for (int mi = 0; mi < 2; mi++)
#pragma unroll
                    for (int ni = 0; ni < 8; ni++)
                        mma_s8(acc[mi][ni], a[mi], b[ni]);
            }
        }
        __syncthreads();   // drain smem reads before next tile's prologue overwrites

        // -------- fused epilogue: logits[m] += sum_n relu(acc*INV_S + b1) * w2 --------
        const int qrow = lid >> 2;
        const int qcol = lid & 3;
#pragma unroll
        for (int mi = 0; mi < 2; mi++) {
            float r0 = 0.f, r1 = 0.f;
#pragma unroll
            for (int ni = 0; ni < 8; ni++) {
                int n = n0 + ni * 8 + qcol * 2;
                float b1a = g_b1[n],     w2a = g_w2[n];
                float b1b = g_b1[n + 1], w2b = g_w2[n + 1];
                r0 += fmaxf(fmaf((float)acc[mi][ni][0], INV_S, b1a), 0.f) * w2a
                    + fmaxf(fmaf((float)acc[mi][ni][1], INV_S, b1b), 0.f) * w2b;
                r1 += fmaxf(fmaf((float)acc[mi][ni][2], INV_S, b1a), 0.f) * w2a
                    + fmaxf(fmaf((float)acc[mi][ni][3], INV_S, b1b), 0.f) * w2b;
            }
            r0 += __shfl_xor_sync(0xffffffffu, r0, 1);
            r0 += __shfl_xor_sync(0xffffffffu, r0, 2);
            r1 += __shfl_xor_sync(0xffffffffu, r1, 1);
            r1 += __shfl_xor_sync(0xffffffffu, r1, 2);
            if (qcol == 0) {
                int row = m0 + wid * 32 + mi * 16 + qrow;
                atomicAdd(&g_logits[row],     r0);
                atomicAdd(&g_logits[row + 8], r1);
            }
        }
    }
}

// ---------------- finalize ----------------
__global__ void finalize(const float* __restrict__ b2, float* __restrict__ out) {
    int i = blockIdx.x * blockDim.x + threadIdx.x;
    if (i < BATCH) {
        float z = g_logits[i] + b2[0];
        out[i] = 1.0f / (1.0f + expf(-z));
    }
}

// ---------------- launch ----------------
extern "C" void kernel_launch(void* const* d_in, const int* in_sizes, int n_in,
                              void* d_out, int out_size) {
    const float* sim = (const float*)d_in[0];
    const float* W1  = (const float*)d_in[1];
    const float* b1  = (const float*)d_in[2];
    const float* W2  = (const float*)d_in[3];
    const float* b2  = (const float*)d_in[4];
    float* out = (float*)d_out;

    cudaFuncSetAttribute(gemm_i8, cudaFuncAttributeMaxDynamicSharedMemorySize, SMEM_TOTAL);

    prep_small<<<(BATCH + 255) / 256, 256>>>(b1, W2);
    prep_w18<<<dim3((KP / 4 + 255) / 256, NP), 256>>>(W1);
    triu8<<<BATCH, 256>>>(sim);
    gemm_i8<<<GRID, 128, SMEM_TOTAL>>>();
    finalize<<<(BATCH + 255) / 256, 256>>>(b2, out);
}

// round 8
// speedup vs baseline: 2.2947x; 2.2947x over previous
#include <cuda_runtime.h>
#include <cuda_bf16.h>
#include <cuda_fp8.h>
#include <cstdint>

#define MDIM  128
#define FEAT  8256          // MDIM*(MDIM+1)/2
#define HID   1651
#define NP    1664          // HID padded to 26*64
#define KP    8320          // FEAT padded to 65*128
#define BATCH 4096
#define KST   65            // KP / 128

#define SCALE_W   8192.0f   // 2^13 on W1 before fp8 (lifts above e4m3 subnormal floor)
#define INV_S     (1.0f/8192.0f)

#define A_BYTES     16384   // 128 rows x 128B
#define B_BYTES     8192    // 64 rows x 128B
#define STAGE_BYTES (A_BYTES + B_BYTES)   // 24 KB
#define NSTAGE      3
#define SMEM_TOTAL  (NSTAGE * STAGE_BYTES)   // 72 KB

#define MT 32               // M tiles (4096/128)
#define NT 26               // N tiles (1664/64)
#define NTILES (MT*NT)      // 832
#define GRID   444          // 148 SMs * 3 CTAs

// ---------------- device scratch ----------------
__device__ uint8_t g_x8 [(size_t)BATCH * KP];   // 34.1 MB fp8
__device__ uint8_t g_w18[(size_t)NP    * KP];   // 13.8 MB fp8
__device__ float g_b1[NP];
__device__ float g_w2[NP];
__device__ float g_logits[BATCH];

// ---------------- helpers ----------------
__device__ __forceinline__ uint32_t smem_u32(const void* p) {
    uint32_t a;
    asm("{ .reg .u64 t; cvta.to.shared.u64 t, %1; cvt.u32.u64 %0, t; }" : "=r"(a) : "l"(p));
    return a;
}
#define SWZ128(off) ((off) ^ (((off) >> 3) & 0x70))

__device__ __forceinline__ void ldsm_x4(uint32_t& r0, uint32_t& r1, uint32_t& r2, uint32_t& r3,
                                        uint32_t addr) {
    asm volatile("ldmatrix.sync.aligned.m8n8.x4.shared.b16 {%0,%1,%2,%3}, [%4];"
                 : "=r"(r0), "=r"(r1), "=r"(r2), "=r"(r3) : "r"(addr));
}
__device__ __forceinline__ void mma_e4m3(float* c, const uint32_t* a, const uint32_t* b) {
    asm volatile(
        "mma.sync.aligned.m16n8k32.row.col.f32.e4m3.e4m3.f32 "
        "{%0,%1,%2,%3}, {%4,%5,%6,%7}, {%8,%9}, {%0,%1,%2,%3};"
        : "+f"(c[0]), "+f"(c[1]), "+f"(c[2]), "+f"(c[3])
        : "r"(a[0]), "r"(a[1]), "r"(a[2]), "r"(a[3]), "r"(b[0]), "r"(b[1]));
}

// ---------------- prep kernels ----------------
__global__ void prep_small(const float* __restrict__ b1, const float* __restrict__ w2) {
    int i = blockIdx.x * blockDim.x + threadIdx.x;
    if (i < NP) {
        g_b1[i] = (i < HID) ? b1[i] : 0.0f;
        g_w2[i] = (i < HID) ? w2[i] : 0.0f;
    }
    if (i < BATCH) g_logits[i] = 0.0f;
}

// W1 fp32 -> fp8 (scaled by 2^13)
__global__ void prep_w18(const float* __restrict__ W1) {
    int n  = blockIdx.y;
    int k4 = blockIdx.x * blockDim.x + threadIdx.x;
    if (k4 >= KP / 4) return;
    uint32_t out = 0;
    if (n < HID) {
        int k = k4 * 4;
        if (k + 3 < FEAT) {
            float4 v = *(const float4*)&W1[(size_t)n * FEAT + k];
            out  = (uint32_t)__nv_cvt_float_to_fp8(v.x * SCALE_W, __NV_SATFINITE, __NV_E4M3);
            out |= (uint32_t)__nv_cvt_float_to_fp8(v.y * SCALE_W, __NV_SATFINITE, __NV_E4M3) << 8;
            out |= (uint32_t)__nv_cvt_float_to_fp8(v.z * SCALE_W, __NV_SATFINITE, __NV_E4M3) << 16;
            out |= (uint32_t)__nv_cvt_float_to_fp8(v.w * SCALE_W, __NV_SATFINITE, __NV_E4M3) << 24;
        } else {
#pragma unroll
            for (int j = 0; j < 4; j++) {
                float v = (k + j < FEAT) ? W1[(size_t)n * FEAT + k + j] * SCALE_W : 0.0f;
                out |= (uint32_t)__nv_cvt_float_to_fp8(v, __NV_SATFINITE, __NV_E4M3) << (8 * j);
            }
        }
    }
    ((uint32_t*)g_w18)[(size_t)n * (KP / 4) + k4] = out;
}

// triu extraction + fp8 convert, float4 loads, lower-triangle groups skipped
__global__ __launch_bounds__(256) void triu8(const float* __restrict__ sim) {
    int b   = blockIdx.x;
    int tid = threadIdx.x;
    const float* base = sim + (size_t)b * MDIM * MDIM;
    uint8_t* out = g_x8 + (size_t)b * KP;
#pragma unroll
    for (int it = 0; it < 16; ++it) {
        int idx = tid + it * 256;       // 0..4095: (row, group-of-4)
        int i = idx >> 5;
        int g = idx & 31;
        int j0 = g * 4;
        if (j0 + 3 >= i) {
            float4 v = *(const float4*)&base[i * MDIM + j0];
            int rowoff = i * MDIM - (i * (i - 1)) / 2 - i;   // out index = rowoff + j
            float vv[4] = {v.x, v.y, v.z, v.w};
#pragma unroll
            for (int l = 0; l < 4; l++) {
                int j = j0 + l;
                if (j >= i)
                    out[rowoff + j] = __nv_cvt_float_to_fp8(vv[l], __NV_SATFINITE, __NV_E4M3);
            }
        }
    }
    if (tid < KP - FEAT) out[FEAT + tid] = 0;
}

// ---------------- fp8 GEMM: persistent, CTA 128x64, 4 warps (32x64), 3 CTA/SM ----------------
__global__ __launch_bounds__(128, 3) void gemm_fp8() {
    extern __shared__ __align__(1024) uint8_t smem[];
    const uint32_t sbase = smem_u32(smem);
    const int tid = threadIdx.x;
    const int wid = tid >> 5;
    const int lid = tid & 31;

    // ---- hoisted ldmatrix addressing (swizzle decomposed: row-invariant XOR mask) ----
    // A: warp wid covers rows [wid*32, wid*32+32); +2048 per 16-row step (row&7 invariant)
    const int aRow0 = wid * 32 + ((lid >> 3) & 1) * 8 + (lid & 7);
    const int aCol  = (lid >> 4) * 16;
    const uint32_t aXor = (uint32_t)((aRow0 & 7) << 4);
    // B: 64 shared rows; +2048 per 16-row step
    const int bRow0 = (lid >> 4) * 8 + (lid & 7);
    const int bCol  = ((lid >> 3) & 1) * 16;
    const uint32_t bXor = (uint32_t)((bRow0 & 7) << 4);

    uint32_t aOff[4], bOff[4];
#pragma unroll
    for (int ks = 0; ks < 4; ks++) {
        aOff[ks] = (uint32_t)(aRow0 * 128) + (((uint32_t)(aCol + ks * 32)) ^ aXor);
        bOff[ks] = A_BYTES + (uint32_t)(bRow0 * 128) + (((uint32_t)(bCol + ks * 32)) ^ bXor);
    }

    for (int t = blockIdx.x; t < NTILES; t += GRID) {
        const int m0 = (t / NT) * 128;
        const int n0 = (t % NT) * 64;

        float acc[2][8][4];
#pragma unroll
        for (int mi = 0; mi < 2; mi++)
#pragma unroll
            for (int ni = 0; ni < 8; ni++)
#pragma unroll
                for (int c = 0; c < 4; c++) acc[mi][ni][c] = 0.0f;

        auto load_stage = [&](int buf, int kByte) {
            uint32_t st = sbase + buf * STAGE_BYTES;
            // A: 1024 chunks (128 rows x 8), B: 512 chunks (64 x 8); 12/thread
#pragma unroll
            for (int it = 0; it < 12; ++it) {
                int idx = tid + it * 128;           // 0..1535
                bool isB = idx >= 1024;
                int rel  = isB ? (idx - 1024) : idx;
                int r    = rel >> 3;
                int c    = rel & 7;
                const uint8_t* src = isB
                    ? &g_w18[(size_t)(n0 + r) * KP + kByte + c * 16]
                    : &g_x8 [(size_t)(m0 + r) * KP + kByte + c * 16];
                uint32_t dst = st + (isB ? A_BYTES : 0) + SWZ128((uint32_t)(r * 128 + c * 16));
                asm volatile("cp.async.cg.shared.global [%0], [%1], 16;"
                             :: "r"(dst), "l"(src) : "memory");
            }
            asm volatile("cp.async.commit_group;" ::: "memory");
        };

        load_stage(0, 0);
        load_stage(1, 128);

        for (int s = 0; s < KST; ++s) {
            asm volatile("cp.async.wait_group 1;" ::: "memory");
            __syncthreads();

            if (s + 2 < KST) load_stage((s + 2) % NSTAGE, (s + 2) * 128);
            else             asm volatile("cp.async.commit_group;" ::: "memory");

            const uint32_t stg = sbase + (s % NSTAGE) * STAGE_BYTES;

#pragma unroll
            for (int ks = 0; ks < 4; ++ks) {
                uint32_t b[8][2];
#pragma unroll
                for (int p = 0; p < 4; p++) {
                    uint32_t r0, r1, r2, r3;
                    ldsm_x4(r0, r1, r2, r3, stg + bOff[ks] + p * 2048);
                    b[2 * p][0] = r0; b[2 * p][1] = r1;
                    b[2 * p + 1][0] = r2; b[2 * p + 1][1] = r3;
                }
                uint32_t a[2][4];
                ldsm_x4(a[0][0], a[0][1], a[0][2], a[0][3], stg + aOff[ks]);
                ldsm_x4(a[1][0], a[1][1], a[1][2], a[1][3], stg + aOff[ks] + 2048);
#pragma unroll
                for (int mi = 0; mi < 2; mi++)
#pragma unroll
                    for (int ni = 0; ni < 8; ni++)
                        mma_e4m3(acc[mi][ni], a[mi], b[ni]);
            }
        }
        __syncthreads();   // drain smem reads before next tile's prologue overwrites

        // -------- fused epilogue: logits[m] += sum_n relu(acc*INV_S + b1) * w2 --------
        const int qrow = lid >> 2;
        const int qcol = lid & 3;
#pragma unroll
        for (int mi = 0; mi < 2; mi++) {
            float r0 = 0.f, r1 = 0.f;
#pragma unroll
            for (int ni = 0; ni < 8; ni++) {
                int n = n0 + ni * 8 + qcol * 2;
                float b1a = g_b1[n],     w2a = g_w2[n];
                float b1b = g_b1[n + 1], w2b = g_w2[n + 1];
                r0 += fmaxf(fmaf(acc[mi][ni][0], INV_S, b1a), 0.f) * w2a
                    + fmaxf(fmaf(acc[mi][ni][1], INV_S, b1b), 0.f) * w2b;
                r1 += fmaxf(fmaf(acc[mi][ni][2], INV_S, b1a), 0.f) * w2a
                    + fmaxf(fmaf(acc[mi][ni][3], INV_S, b1b), 0.f) * w2b;
            }
            r0 += __shfl_xor_sync(0xffffffffu, r0, 1);
            r0 += __shfl_xor_sync(0xffffffffu, r0, 2);
            r1 += __shfl_xor_sync(0xffffffffu, r1, 1);
            r1 += __shfl_xor_sync(0xffffffffu, r1, 2);
            if (qcol == 0) {
                int row = m0 + wid * 32 + mi * 16 + qrow;
                atomicAdd(&g_logits[row],     r0);
                atomicAdd(&g_logits[row + 8], r1);
            }
        }
    }
}

// ---------------- finalize ----------------
__global__ void finalize(const float* __restrict__ b2, float* __restrict__ out) {
    int i = blockIdx.x * blockDim.x + threadIdx.x;
    if (i < BATCH) {
        float z = g_logits[i] + b2[0];
        out[i] = 1.0f / (1.0f + expf(-z));
    }
}

// ---------------- launch ----------------
extern "C" void kernel_launch(void* const* d_in, const int* in_sizes, int n_in,
                              void* d_out, int out_size) {
    const float* sim = (const float*)d_in[0];
    const float* W1  = (const float*)d_in[1];
    const float* b1  = (const float*)d_in[2];
    const float* W2  = (const float*)d_in[3];
    const float* b2  = (const float*)d_in[4];
    float* out = (float*)d_out;

    cudaFuncSetAttribute(gemm_fp8, cudaFuncAttributeMaxDynamicSharedMemorySize, SMEM_TOTAL);

    prep_small<<<(BATCH + 255) / 256, 256>>>(b1, W2);
    prep_w18<<<dim3((KP / 4 + 255) / 256, NP), 256>>>(W1);
    triu8<<<BATCH, 256>>>(sim);
    gemm_fp8<<<GRID, 128, SMEM_TOTAL>>>();
    finalize<<<(BATCH + 255) / 256, 256>>>(b2, out);
}